// round 11
// baseline (speedup 1.0000x reference)
#include <cuda_runtime.h>
#include <cuda_fp16.h>
#include <math.h>
#include <stdint.h>

// ---------------- problem constants ----------------
#define BATCH 16384
#define HID   256

#define OFF_HNEXT 0
#define OFF_GS    (BATCH * HID)
#define OFF_GNODE (OFF_GS + 9)
#define OFF_MARG  (OFF_GNODE + BATCH * 9 * HID)
#define GROW      (9 * HID)

#define EPI_NONE 0
#define EPI_SIG  1
#define EPI_ADD  2
#define EPI_MUL  3
#define EPI_OMZ  4

#define C3_ADD 0
#define C3_OMZ 1
#define C3_MUL 2

// ---------------- scratch (fp16 intermediates) ----------------
__device__ __half g_hL[BATCH * 768];
__device__ __half g_tmp[BATCH * 768];
__device__ __half g_cand[BATCH * 768];
__device__ __half g_cand2[BATCH * 768];
__device__ float g_rows[6 * 4 * BATCH];
__device__ double g_ssum[24];

#define UNIT (BATCH * HID)
// fp16 activations: 0:x 1:h 2,3:z1r(ld512) 4:rh 5:ht 6:om 7:zt 8:z2h
__device__ __half g_hf[9ull * UNIT];
#define WUNIT (4 * 256 * 256)
__device__ __half g_wh[4 * WUNIT];

// ---------------- helpers ----------------
__device__ __forceinline__ uint32_t smem_u32(const void* p) {
    uint32_t a;
    asm("{ .reg .u64 t; cvta.to.shared.u64 t, %1; cvt.u32.u64 %0, t; }" : "=r"(a) : "l"(p));
    return a;
}
#define CP16(saddr, gaddr) \
    asm volatile("cp.async.ca.shared.global [%0], [%1], 16;" :: "r"(saddr), "l"(gaddr))
#define CP_COMMIT() asm volatile("cp.async.commit_group;")
#define CP_WAIT1()  asm volatile("cp.async.wait_group 1;")
#define CP_WAIT0()  asm volatile("cp.async.wait_group 0;")

__device__ __forceinline__ void ldm_x4(uint32_t* r, uint32_t addr) {
    asm volatile("ldmatrix.sync.aligned.m8n8.x4.shared.b16 {%0,%1,%2,%3}, [%4];"
                 : "=r"(r[0]), "=r"(r[1]), "=r"(r[2]), "=r"(r[3]) : "r"(addr));
}
__device__ __forceinline__ void mma_f16(float* d, const uint32_t* a, const uint32_t* b) {
    asm volatile(
        "mma.sync.aligned.m16n8k16.row.col.f32.f16.f16.f32 "
        "{%0,%1,%2,%3}, {%4,%5,%6,%7}, {%8,%9}, {%0,%1,%2,%3};"
        : "+f"(d[0]), "+f"(d[1]), "+f"(d[2]), "+f"(d[3])
        : "r"(a[0]), "r"(a[1]), "r"(a[2]), "r"(a[3]), "r"(b[0]), "r"(b[1]));
}

// ---------------- GEMM job ----------------
struct GJob {
    const __half *A1, *A2;
    const __half *W1h, *W1l, *W2h, *W2l;
    const float *bias;
    const __half *Dh, *D2h;      // fp16 elementwise operands
    float *C;                    // fp32 output (gnode) - optional
    __half *Ch, *C2h;            // fp16 outputs (scratch) - optional
    __half *Ob;                  // fp16 activation copy
    int lda1, lda2, nPair, ldd, ldc, mode, ldd2, ldc2, mode2, ldob, dupz2;
};

// tile 128x64, warp 32x32, 8 warps, 2-stage cp.async
#define LDSE 40
#define A_T (128 * LDSE * 2)     // 10240
#define B_T (64 * LDSE * 2)      // 5120
#define STAGE_B (A_T + 2 * B_T)  // 20480
#define DYN_SMEM (2 * STAGE_B)   // 40960

__device__ __forceinline__ void gemm_body(const GJob& J, int xt, char* smc, uint32_t smb)
{
    const int tid  = threadIdx.x;
    const int wid  = tid >> 5;
    const int lane = tid & 31;

    const int row0   = blockIdx.y * 128;
    const int n0     = xt * 64;
    const int kslice = n0 >> 8;
    const int wc0    = n0 & 255;

    const __half* wBh1 = J.W1h + kslice * 65536;
    const __half* wBl1 = J.W1l + kslice * 65536;
    const __half* wBh2 = J.W2h ? J.W2h + kslice * 65536 : (const __half*)0;
    const __half* wBl2 = J.W2l ? J.W2l + kslice * 65536 : (const __half*)0;

    const int NCH = J.nPair * 8;

    const int lrowA = tid >> 1;
    const int lkofA = (tid & 1) * 16;
    const int lrowB = tid >> 2;
    const int lkofB = (tid & 3) * 8;

    float acc[32];
#pragma unroll
    for (int i = 0; i < 32; i++) acc[i] = 0.f;

    const int wm = (wid >> 1) * 32;
    const int wn = (wid & 1) * 32;

    auto load_chunk = [&](int c, int buf) {
        const __half *pA, *pWh, *pWl;
        int lda;
        if (c < 8) { pA = J.A1; lda = J.lda1; pWh = wBh1; pWl = wBl1; }
        else       { pA = J.A2; lda = J.lda2; pWh = wBh2; pWl = wBl2; }
        const int k0 = (c & 7) * 32;
        const uint32_t sb = smb + buf * STAGE_B;
        const uint32_t soA = (lrowA * LDSE + lkofA) * 2;
        const __half* gA = pA + (size_t)(row0 + lrowA) * lda + k0 + lkofA;
        CP16(sb + soA,      gA);
        CP16(sb + soA + 16, gA + 8);
        const uint32_t soB = (lrowB * LDSE + lkofB) * 2;
        CP16(sb + A_T + soB,       pWh + (size_t)(wc0 + lrowB) * 256 + k0 + lkofB);
        CP16(sb + A_T + B_T + soB, pWl + (size_t)(wc0 + lrowB) * 256 + k0 + lkofB);
        CP_COMMIT();
    };

    load_chunk(0, 0);

    const uint32_t aRow  = (uint32_t)(wm + (lane & 15));
    const uint32_t aKh   = (uint32_t)((lane >> 4) * 8);
    const uint32_t bRow2 = (uint32_t)(wn + (lane & 7) + ((lane >> 4) * 8));
    const uint32_t bKc   = (uint32_t)(((lane >> 3) & 1) * 8);

    for (int c = 0; c < NCH; c++) {
        if (c + 1 < NCH) { load_chunk(c + 1, (c + 1) & 1); CP_WAIT1(); }
        else             { CP_WAIT0(); }
        __syncthreads();

        const uint32_t sb = smb + (c & 1) * STAGE_B;
#pragma unroll
        for (int ks = 0; ks < 2; ks++) {
            uint32_t a[2][4];
#pragma unroll
            for (int i = 0; i < 2; i++)
                ldm_x4(a[i], sb + ((aRow + i * 16) * LDSE + ks * 16 + aKh) * 2);
#pragma unroll
            for (int jp = 0; jp < 2; jp++) {
                uint32_t bh4[4], bl4[4];
                const uint32_t boff = ((bRow2 + jp * 16) * LDSE + ks * 16 + bKc) * 2;
                ldm_x4(bh4, sb + A_T + boff);
                ldm_x4(bl4, sb + A_T + B_T + boff);
#pragma unroll
                for (int i = 0; i < 2; i++) {
                    float* d0 = &acc[(i * 4 + jp * 2) * 4];
                    float* d1 = &acc[(i * 4 + jp * 2 + 1) * 4];
                    mma_f16(d0, a[i], bh4);
                    mma_f16(d0, a[i], bl4);
                    mma_f16(d1, a[i], bh4 + 2);
                    mma_f16(d1, a[i], bl4 + 2);
                }
            }
        }
        __syncthreads();
    }

    // epilogue: regs -> smem (128 x 68 f32) -> gmem
    float* smf = (float*)smc;
    {
        const int r0 = lane >> 2;
        const int cc = (lane & 3) * 2;
#pragma unroll
        for (int i = 0; i < 2; i++)
#pragma unroll
            for (int j = 0; j < 4; j++) {
                const float* d = &acc[(i * 4 + j) * 4];
                const int rr = wm + i * 16 + r0;
                const int col = wn + j * 8 + cc;
                smf[rr * 68 + col]           = d[0];
                smf[rr * 68 + col + 1]       = d[1];
                smf[(rr + 8) * 68 + col]     = d[2];
                smf[(rr + 8) * 68 + col + 1] = d[3];
            }
    }
    __syncthreads();

    const bool c_vec = J.C && ((((uintptr_t)J.C) & 15) == 0) && ((J.ldc & 3) == 0);

#pragma unroll
    for (int it = 0; it < 8; it++) {
        const int f4 = it * 256 + tid;
        const int rr = f4 >> 4;
        const int c4 = (f4 & 15) * 4;
        float4 v = *(float4*)&smf[rr * 68 + c4];
        const int row = row0 + rr;
        const int gn  = n0 + c4;
        float o[4];
        float dv[4] = {0.f, 0.f, 0.f, 0.f};
        if (J.mode == EPI_ADD || J.mode == EPI_MUL) {
            const __half2* dp = (const __half2*)(J.Dh + (size_t)row * J.ldd + gn);
            float2 a0 = __half22float2(dp[0]);
            float2 a1 = __half22float2(dp[1]);
            dv[0] = a0.x; dv[1] = a0.y; dv[2] = a1.x; dv[3] = a1.y;
        }
#pragma unroll
        for (int q = 0; q < 4; q++) {
            const float val = (&v.x)[q];
            const float bv = J.bias ? J.bias[gn + q] : 0.f;
            float res;
            if (J.mode == EPI_SIG)      res = 1.f / (1.f + expf(-(val + bv)));
            else if (J.mode == EPI_ADD) res = val + dv[q] + bv;
            else if (J.mode == EPI_MUL) res = val * dv[q] + bv;
            else if (J.mode == EPI_OMZ) res = 1.f - (val + bv);
            else                        res = val + bv;
            o[q] = res;
        }
        if (J.Ch) {
            __half2* cp = (__half2*)(J.Ch + (size_t)row * J.ldc + gn);
            cp[0] = __floats2half2_rn(o[0], o[1]);
            cp[1] = __floats2half2_rn(o[2], o[3]);
        } else if (J.C) {
            float* cp = J.C + (size_t)row * J.ldc + gn;
            if (c_vec) *(float4*)cp = make_float4(o[0], o[1], o[2], o[3]);
            else { cp[0] = o[0]; cp[1] = o[1]; cp[2] = o[2]; cp[3] = o[3]; }
            if (J.dupz2 && gn < 256) {
                float* zp = J.C + (size_t)row * J.ldc + 512 + gn;
                zp[0] = o[0]; zp[1] = o[1]; zp[2] = o[2]; zp[3] = o[3];
            }
        }

        if (J.C2h) {
            float o2[4];
            float dv2[4] = {0.f, 0.f, 0.f, 0.f};
            if (J.mode2 == EPI_ADD || J.mode2 == EPI_MUL) {
                const __half2* dp = (const __half2*)(J.D2h + (size_t)row * J.ldd2 + gn);
                float2 a0 = __half22float2(dp[0]);
                float2 a1 = __half22float2(dp[1]);
                dv2[0] = a0.x; dv2[1] = a0.y; dv2[2] = a1.x; dv2[3] = a1.y;
            }
#pragma unroll
            for (int q = 0; q < 4; q++) {
                const float val = (&v.x)[q];
                const float bv = J.bias ? J.bias[gn + q] : 0.f;
                float res;
                if (J.mode2 == EPI_SIG)      res = 1.f / (1.f + expf(-(val + bv)));
                else if (J.mode2 == EPI_ADD) res = val + dv2[q] + bv;
                else if (J.mode2 == EPI_MUL) res = val * dv2[q] + bv;
                else if (J.mode2 == EPI_OMZ) res = 1.f - (val + bv);
                else                         res = val + bv;
                o2[q] = res;
            }
            __half2* cp2 = (__half2*)(J.C2h + (size_t)row * J.ldc2 + gn);
            cp2[0] = __floats2half2_rn(o2[0], o2[1]);
            cp2[1] = __floats2half2_rn(o2[2], o2[3]);
        }

        if (J.Ob) {
            __half2* ph = (__half2*)(J.Ob + (size_t)row * J.ldob + gn);
            ph[0] = __floats2half2_rn(o[0], o[1]);
            ph[1] = __floats2half2_rn(o[2], o[3]);
        }
    }
}

__global__ __launch_bounds__(256, 3)
void tc_gemm2(GJob j0, GJob j1, int nx0)
{
    extern __shared__ char smc[];
    const uint32_t smb = smem_u32(smc);
    if ((int)blockIdx.x < nx0) gemm_body(j0, blockIdx.x, smc, smb);
    else                       gemm_body(j1, blockIdx.x - nx0, smc, smb);
}

// ---------------- prep: weights transpose+split + input convert ----------
__global__ __launch_bounds__(256)
void prep_all(const float* __restrict__ L, const float* __restrict__ R,
              const float* __restrict__ x, const float* __restrict__ h,
              __half* __restrict__ Lh, __half* __restrict__ Ll,
              __half* __restrict__ Rh, __half* __restrict__ Rl,
              __half* __restrict__ xf, __half* __restrict__ hf)
{
    __shared__ float t[32][33];
    const int bid = blockIdx.x;
    if (bid < 512) {
        const int mz = bid >> 6;
        const int rem = bid & 63;
        const int h0 = (rem >> 3) * 32, d0 = (rem & 7) * 32;
        const float* src = (mz < 4) ? L : R;
        __half* dh = (mz < 4) ? Lh : Rh;
        __half* dl = (mz < 4) ? Ll : Rl;
        const int k = mz & 3;
        const int tx = threadIdx.x & 31, ty = threadIdx.x >> 5;
        for (int i = 0; i < 32; i += 8)
            t[ty + i][tx] = src[k * 65536 + (h0 + ty + i) * 256 + d0 + tx];
        __syncthreads();
        for (int i = 0; i < 32; i += 8) {
            const float v = t[tx][ty + i];
            const __half hi = __float2half_rn(v);
            const __half lo = __float2half_rn(v - __half2float(hi));
            dh[k * 65536 + (d0 + ty + i) * 256 + h0 + tx] = hi;
            dl[k * 65536 + (d0 + ty + i) * 256 + h0 + tx] = lo;
        }
    } else {
        const int i = (bid - 512) * 256 + threadIdx.x;
        const int n = BATCH * HID;
        if (i < n) xf[i] = __float2half_rn(x[i]);
        else       hf[i - n] = __float2half_rn(h[i - n]);
    }
}

// ---------------- mixture (multi-job), fp16 candidates ----------------
struct MJob {
    const __half *cand;
    const float *P, *Q;
    float *out1, *out2;
    __half *ob;
    float *rows;
    int ldcand, ldp, ldq, c3mode, ldo1;
};

__device__ __forceinline__ void mix_body(const MJob& M, int local,
                                         const float* __restrict__ b3,
                                         const float* __restrict__ Ws)
{
    const int warp = threadIdx.x >> 5;
    const int lane = threadIdx.x & 31;
    const int b = local * 8 + warp;
    const int j = lane * 8;

    const __half* cr = M.cand + (size_t)b * M.ldcand;
    const float* pr = M.P + (size_t)b * M.ldp;
    const float* qr = M.Q ? M.Q + (size_t)b * M.ldq : (const float*)0;

    float c0[8], c1[8], c2[8], c3v[8];
    {
        uint4 u0 = *(const uint4*)(cr + j);
        uint4 u1 = *(const uint4*)(cr + 256 + j);
        uint4 u2 = *(const uint4*)(cr + 512 + j);
        const __half2* p0 = (const __half2*)&u0;
        const __half2* p1 = (const __half2*)&u1;
        const __half2* p2 = (const __half2*)&u2;
#pragma unroll
        for (int e = 0; e < 4; e++) {
            float2 f0 = __half22float2(p0[e]);
            float2 f1 = __half22float2(p1[e]);
            float2 f2 = __half22float2(p2[e]);
            c0[2 * e] = f0.x; c0[2 * e + 1] = f0.y;
            c1[2 * e] = f1.x; c1[2 * e + 1] = f1.y;
            c2[2 * e] = f2.x; c2[2 * e + 1] = f2.y;
        }
    }
    float pv[8];
#pragma unroll
    for (int e = 0; e < 8; e++) pv[e] = pr[j + e];   // gnode: 4B-aligned, scalar
    if (M.c3mode == C3_ADD) {
#pragma unroll
        for (int e = 0; e < 8; e++) c3v[e] = pv[e] + qr[j + e] + b3[j + e];
    } else if (M.c3mode == C3_OMZ) {
#pragma unroll
        for (int e = 0; e < 8; e++) c3v[e] = 1.f - (pv[e] + b3[j + e]);
    } else {
#pragma unroll
        for (int e = 0; e < 8; e++) c3v[e] = pv[e] * qr[j + e] + b3[j + e];
    }

    float s0 = 0.f, s1 = 0.f, s2 = 0.f, s3 = 0.f;
    float wv[8];
    {
        float4 wa = *(const float4*)(Ws + j);
        float4 wb = *(const float4*)(Ws + j + 4);
        wv[0] = wa.x; wv[1] = wa.y; wv[2] = wa.z; wv[3] = wa.w;
        wv[4] = wb.x; wv[5] = wb.y; wv[6] = wb.z; wv[7] = wb.w;
    }
#pragma unroll
    for (int e = 0; e < 8; e++) {
        s0 += c0[e] * wv[e];
        s1 += c1[e] * wv[e];
        s2 += c2[e] * wv[e];
        s3 += c3v[e] * wv[e];
    }

#pragma unroll
    for (int o = 16; o > 0; o >>= 1) {
        s0 += __shfl_xor_sync(0xffffffffu, s0, o);
        s1 += __shfl_xor_sync(0xffffffffu, s1, o);
        s2 += __shfl_xor_sync(0xffffffffu, s2, o);
        s3 += __shfl_xor_sync(0xffffffffu, s3, o);
    }

    if (lane < 4) {
        const float sv = (lane == 0) ? s0 : (lane == 1) ? s1 : (lane == 2) ? s2 : s3;
        M.rows[lane * BATCH + b] = sv;
    }

    const float mx = fmaxf(fmaxf(s0, s1), fmaxf(s2, s3));
    const float e0 = expf(s0 - mx), e1 = expf(s1 - mx);
    const float e2 = expf(s2 - mx), e3 = expf(s3 - mx);
    const float inv = 1.f / (e0 + e1 + e2 + e3);
    const float w0 = e0 * inv, w1 = e1 * inv, w2 = e2 * inv, w3 = e3 * inv;

    float o[8];
#pragma unroll
    for (int e = 0; e < 8; e++)
        o[e] = w0 * c0[e] + w1 * c1[e] + w2 * c2[e] + w3 * c3v[e];

    float* op = M.out1 + (size_t)b * M.ldo1 + j;
#pragma unroll
    for (int e = 0; e < 8; e++) op[e] = o[e];    // gnode 4B-aligned: scalar
    if (M.out2) {
        float* o2 = M.out2 + (size_t)b * HID + j;
        *(float4*)o2       = make_float4(o[0], o[1], o[2], o[3]);
        *(float4*)(o2 + 4) = make_float4(o[4], o[5], o[6], o[7]);
    }
    if (M.ob) {
        uint4 u;
        __half2* ph = (__half2*)&u;
        ph[0] = __floats2half2_rn(o[0], o[1]);
        ph[1] = __floats2half2_rn(o[2], o[3]);
        ph[2] = __floats2half2_rn(o[4], o[5]);
        ph[3] = __floats2half2_rn(o[6], o[7]);
        *(uint4*)(M.ob + (size_t)b * HID + j) = u;
    }
}

__global__ __launch_bounds__(256)
void mix3(MJob m0, MJob m1, MJob m2, const float* b3, const float* Ws)
{
    const int jid = blockIdx.x >> 11;
    const int local = blockIdx.x & 2047;
    if (jid == 0)      mix_body(m0, local, b3, Ws);
    else if (jid == 1) mix_body(m1, local, b3, Ws);
    else               mix_body(m2, local, b3, Ws);
}

// ---------------- finalize ----------------
__global__ __launch_bounds__(256)
void fin_sum(const float* __restrict__ rs)
{
    __shared__ double tmp[256];
    const int idx = blockIdx.x;
    const int tid = threadIdx.x;
    double p = 0.0;
    for (int i = tid; i < BATCH; i += 256) p += (double)rs[idx * BATCH + i];
    tmp[tid] = p;
    __syncthreads();
    for (int o = 128; o > 0; o >>= 1) {
        if (tid < o) tmp[tid] += tmp[tid + o];
        __syncthreads();
    }
    if (tid == 0) g_ssum[idx] = tmp[0];
}

__global__ void fin_out(float* __restrict__ out)
{
    if (threadIdx.x == 0) {
        out[OFF_GS + 0] = 0.f;
        out[OFF_GS + 1] = 1.f;
        out[OFF_GS + 2] = 0.f;
        for (int s = 0; s < 6; s++) {
            double best = g_ssum[s * 4]; int bi = 0;
            for (int k = 1; k < 4; k++)
                if (g_ssum[s * 4 + k] > best) { best = g_ssum[s * 4 + k]; bi = k; }
            double second = -1e300;
            for (int k = 0; k < 4; k++)
                if (k != bi && g_ssum[s * 4 + k] > second) second = g_ssum[s * 4 + k];
            out[OFF_GS + 3 + s] = (float)bi;
            out[OFF_MARG + s]   = (float)(best - second);
        }
    }
}

// ---------------- launcher ----------------
extern "C" void kernel_launch(void* const* d_in, const int* in_sizes, int n_in,
                              void* d_out, int out_size)
{
    const float* x  = (const float*)d_in[0];
    const float* h  = (const float*)d_in[1];
    const float* L  = (const float*)d_in[2];
    const float* R  = (const float*)d_in[3];
    const float* bb = (const float*)d_in[4];
    const float* Ws = (const float*)d_in[5];
    float* out = (float*)d_out;

    static bool attr_done = false;
    if (!attr_done) {
        cudaFuncSetAttribute(tc_gemm2, cudaFuncAttributeMaxDynamicSharedMemorySize, DYN_SMEM);
        attr_done = true;
    }

    __half *p_hL, *p_tmp, *p_cand, *p_cand2, *p_hf, *p_w;
    float *p_rows;
    cudaGetSymbolAddress((void**)&p_hL,    g_hL);
    cudaGetSymbolAddress((void**)&p_tmp,   g_tmp);
    cudaGetSymbolAddress((void**)&p_cand,  g_cand);
    cudaGetSymbolAddress((void**)&p_cand2, g_cand2);
    cudaGetSymbolAddress((void**)&p_rows,  g_rows);
    cudaGetSymbolAddress((void**)&p_hf,    g_hf);
    cudaGetSymbolAddress((void**)&p_w,     g_wh);

    __half* xf   = p_hf + 0ull * UNIT;
    __half* hf   = p_hf + 1ull * UNIT;
    __half* z1r  = p_hf + 2ull * UNIT;   // 2 units, ld 512
    __half* rh   = p_hf + 4ull * UNIT;
    __half* ht   = p_hf + 5ull * UNIT;
    __half* om   = p_hf + 6ull * UNIT;
    __half* zt   = p_hf + 7ull * UNIT;
    __half* z2h  = p_hf + 8ull * UNIT;

    __half* Lh = p_w + 0ull * WUNIT;
    __half* Ll = p_w + 1ull * WUNIT;
    __half* Rh = p_w + 2ull * WUNIT;
    __half* Rl = p_w + 3ull * WUNIT;

    float* gnode = out + OFF_GNODE;
    const float* b3 = bb + 768;
    const dim3 blk(256);

    prep_all<<<512 + 2 * UNIT / 256, blk>>>(L, R, x, h, Lh, Ll, Rh, Rl, xf, hf);

    // ---- GEMM jobs
    GJob jS0{}; // [z1|r] = sig(x@L + h@R + b), N=512, fp32 -> gnode (+dup z2)
    jS0.A1 = xf; jS0.lda1 = 256; jS0.W1h = Lh; jS0.W1l = Ll;
    jS0.A2 = hf; jS0.lda2 = 256; jS0.W2h = Rh; jS0.W2l = Rl;
    jS0.nPair = 2; jS0.bias = bb;
    jS0.C = gnode; jS0.ldc = GROW; jS0.mode = EPI_SIG;
    jS0.Ob = z1r; jS0.ldob = 512; jS0.dupz2 = 1;

    GJob jHL{}; // hL = h @ L[0..2]  (fp16 scratch)
    jHL.A1 = hf; jHL.lda1 = 256; jHL.W1h = Lh; jHL.W1l = Ll;
    jHL.nPair = 1;
    jHL.Ch = p_hL; jHL.ldc = 768; jHL.mode = EPI_NONE;

    GJob jCE{}; // v = z1@R; cand_C = 1-(v+b) -> cand ; cand_E = v*hL + b -> tmp
    jCE.A1 = z1r; jCE.lda1 = 512; jCE.W1h = Rh; jCE.W1l = Rl;
    jCE.nPair = 1; jCE.bias = bb;
    jCE.Ch = p_cand; jCE.ldc = 768; jCE.mode = EPI_OMZ;
    jCE.D2h = p_hL; jCE.ldd2 = 768; jCE.C2h = p_tmp; jCE.ldc2 = 768; jCE.mode2 = EPI_MUL;

    GJob jA{};  // cand_A = r@R + hL + b -> cand2
    jA.A1 = z1r + 256; jA.lda1 = 512; jA.W1h = Rh; jA.W1l = Rl;
    jA.nPair = 1; jA.bias = bb;
    jA.Dh = p_hL; jA.ldd = 768;
    jA.Ch = p_cand2; jA.ldc = 768; jA.mode = EPI_ADD;

    GJob jB{};  // cand_B = x@L + rh@R + b -> cand
    jB.A1 = xf; jB.lda1 = 256; jB.W1h = Lh; jB.W1l = Ll;
    jB.A2 = rh; jB.lda2 = 256; jB.W2h = Rh; jB.W2l = Rl;
    jB.nPair = 2; jB.bias = bb;
    jB.Ch = p_cand; jB.ldc = 768; jB.mode = EPI_NONE;

    GJob jOR{}; // omzR = omz@R -> tmp (no bias)
    jOR.A1 = om; jOR.lda1 = 256; jOR.W1h = Rh; jOR.W1l = Rl;
    jOR.nPair = 1;
    jOR.Ch = p_tmp; jOR.ldc = 768; jOR.mode = EPI_NONE;

    GJob jD{};  // cand_D = (ht@L) * omzR + b -> cand2
    jD.A1 = ht; jD.lda1 = 256; jD.W1h = Lh; jD.W1l = Ll;
    jD.nPair = 1; jD.bias = bb;
    jD.Dh = p_tmp; jD.ldd = 768;
    jD.Ch = p_cand2; jD.ldc = 768; jD.mode = EPI_MUL;

    GJob jF{};  // cand_F = zt@L + z2h@R + b -> cand
    jF.A1 = zt; jF.lda1 = 256; jF.W1h = Lh; jF.W1l = Ll;
    jF.A2 = z2h; jF.lda2 = 256; jF.W2h = Rh; jF.W2l = Rl;
    jF.nPair = 2; jF.bias = bb;
    jF.Ch = p_cand; jF.ldc = 768; jF.mode = EPI_NONE;

    // ---- mix jobs
    MJob mC{}; mC.cand = p_cand; mC.ldcand = 768; mC.P = gnode; mC.ldp = GROW;
    mC.c3mode = C3_OMZ; mC.out1 = gnode + 5 * HID; mC.ldo1 = GROW;
    mC.ob = om; mC.rows = p_rows + 2 * 4 * BATCH;

    MJob mE{}; mE.cand = p_tmp; mE.ldcand = 768; mE.P = h; mE.ldp = HID;
    mE.Q = gnode; mE.ldq = GROW; mE.c3mode = C3_MUL;
    mE.out1 = gnode + 7 * HID; mE.ldo1 = GROW;
    mE.ob = z2h; mE.rows = p_rows + 4 * 4 * BATCH;

    MJob mA{}; mA.cand = p_cand2; mA.ldcand = 768; mA.P = h; mA.ldp = HID;
    mA.Q = gnode + 1 * HID; mA.ldq = GROW; mA.c3mode = C3_ADD;
    mA.out1 = gnode + 3 * HID; mA.ldo1 = GROW;
    mA.ob = rh; mA.rows = p_rows + 0 * 4 * BATCH;

    MJob mB{}; mB.cand = p_cand; mB.ldcand = 768; mB.P = x; mB.ldp = HID;
    mB.Q = gnode + 3 * HID; mB.ldq = GROW; mB.c3mode = C3_ADD;
    mB.out1 = gnode + 4 * HID; mB.ldo1 = GROW;
    mB.ob = ht; mB.rows = p_rows + 1 * 4 * BATCH;

    MJob mD{}; mD.cand = p_cand2; mD.ldcand = 768; mD.P = gnode + 4 * HID; mD.ldp = GROW;
    mD.Q = gnode + 5 * HID; mD.ldq = GROW; mD.c3mode = C3_MUL;
    mD.out1 = gnode + 6 * HID; mD.ldo1 = GROW;
    mD.ob = zt; mD.rows = p_rows + 3 * 4 * BATCH;

    MJob mF{}; mF.cand = p_cand; mF.ldcand = 768; mF.P = gnode + 6 * HID; mF.ldp = GROW;
    mF.Q = gnode + 7 * HID; mF.ldq = GROW; mF.c3mode = C3_ADD;
    mF.out1 = gnode + 8 * HID; mF.ldo1 = GROW; mF.out2 = out + OFF_HNEXT;
    mF.rows = p_rows + 5 * 4 * BATCH;

    // wave 1: stage0 (8 tiles) + hL (12 tiles)
    tc_gemm2<<<dim3(20, BATCH / 128), blk, DYN_SMEM>>>(jS0, jHL, 8);
    // wave 2: CE (12) + A (12)
    tc_gemm2<<<dim3(24, BATCH / 128), blk, DYN_SMEM>>>(jCE, jA, 12);
    // wave 3: mix C, E, A
    mix3<<<3 * 2048, blk>>>(mC, mE, mA, b3, Ws);
    // wave 4: B (12) + omzR (12)
    tc_gemm2<<<dim3(24, BATCH / 128), blk, DYN_SMEM>>>(jB, jOR, 12);
    // wave 5: mix B
    mix3<<<2048, blk>>>(mB, mB, mB, b3, Ws);
    // wave 6: D
    tc_gemm2<<<dim3(12, BATCH / 128), blk, DYN_SMEM>>>(jD, jD, 12);
    // wave 7: mix D
    mix3<<<2048, blk>>>(mD, mD, mD, b3, Ws);
    // wave 8: F
    tc_gemm2<<<dim3(12, BATCH / 128), blk, DYN_SMEM>>>(jF, jF, 12);
    // wave 9: mix F
    mix3<<<2048, blk>>>(mF, mF, mF, b3, Ws);

    fin_sum<<<24, blk>>>(p_rows);
    fin_out<<<1, 32>>>(out);
}

// round 12
// speedup vs baseline: 1.2191x; 1.2191x over previous
#include <cuda_runtime.h>
#include <cuda_fp16.h>
#include <math.h>
#include <stdint.h>

// ---------------- problem constants ----------------
#define BATCH 16384
#define HID   256

#define OFF_HNEXT 0
#define OFF_GS    (BATCH * HID)
#define OFF_GNODE (OFF_GS + 9)
#define OFF_MARG  (OFF_GNODE + BATCH * 9 * HID)
#define GROW      (9 * HID)

#define EPI_NONE 0
#define EPI_SIG  1
#define EPI_ADD  2
#define EPI_MUL  3
#define EPI_OMZ  4

#define C3_ADD 0
#define C3_OMZ 1
#define C3_MUL 2

// ---------------- scratch (fp16 intermediates) ----------------
__device__ __half g_hL[BATCH * 768];
__device__ __half g_tmp[BATCH * 768];
__device__ __half g_cand[BATCH * 768];
__device__ __half g_cand2[BATCH * 768];
__device__ float g_rows[6 * 4 * BATCH];
__device__ double g_ssum[24];

#define UNIT (BATCH * HID)
// fp16 activations: 0:x 1:h 2,3:z1r(ld512) 4:rh 5:ht 6:om 7:zt 8:z2h
__device__ __half g_hf[9ull * UNIT];
#define WUNIT (4 * 256 * 256)
// fp16 weights K-major [d][h]: Lh, Rh
__device__ __half g_wh[2 * WUNIT];

// ---------------- helpers ----------------
__device__ __forceinline__ uint32_t smem_u32(const void* p) {
    uint32_t a;
    asm("{ .reg .u64 t; cvta.to.shared.u64 t, %1; cvt.u32.u64 %0, t; }" : "=r"(a) : "l"(p));
    return a;
}
#define CP16(saddr, gaddr) \
    asm volatile("cp.async.ca.shared.global [%0], [%1], 16;" :: "r"(saddr), "l"(gaddr))
#define CP_COMMIT() asm volatile("cp.async.commit_group;")
#define CP_WAIT2()  asm volatile("cp.async.wait_group 2;")
#define CP_WAIT1()  asm volatile("cp.async.wait_group 1;")
#define CP_WAIT0()  asm volatile("cp.async.wait_group 0;")

__device__ __forceinline__ void ldm_x4(uint32_t* r, uint32_t addr) {
    asm volatile("ldmatrix.sync.aligned.m8n8.x4.shared.b16 {%0,%1,%2,%3}, [%4];"
                 : "=r"(r[0]), "=r"(r[1]), "=r"(r[2]), "=r"(r[3]) : "r"(addr));
}
__device__ __forceinline__ void mma_f16(float* d, const uint32_t* a, const uint32_t* b) {
    asm volatile(
        "mma.sync.aligned.m16n8k16.row.col.f32.f16.f16.f32 "
        "{%0,%1,%2,%3}, {%4,%5,%6,%7}, {%8,%9}, {%0,%1,%2,%3};"
        : "+f"(d[0]), "+f"(d[1]), "+f"(d[2]), "+f"(d[3])
        : "r"(a[0]), "r"(a[1]), "r"(a[2]), "r"(a[3]), "r"(b[0]), "r"(b[1]));
}

// ---------------- GEMM job ----------------
struct GJob {
    const __half *A1, *A2;
    const __half *W1, *W2;       // single fp16 weights (K-major [d][h])
    const float *bias;
    const __half *Dh, *D2h;      // fp16 elementwise operands
    float *C;                    // fp32 output (gnode) - optional
    __half *Ch, *C2h;            // fp16 outputs (scratch) - optional
    __half *Ob;                  // fp16 activation copy
    int lda1, lda2, nPair, ldd, ldc, mode, ldd2, ldc2, mode2, ldob, dupz2;
};

// tile 128x64, warp 32x32, 8 warps, 3-stage cp.async ring
#define LDSE 40
#define A_T (128 * LDSE * 2)     // 10240
#define B_T (64 * LDSE * 2)      // 5120
#define STAGE_B (A_T + B_T)      // 15360
#define DYN_SMEM (3 * STAGE_B)   // 46080

__device__ __forceinline__ void gemm_body(const GJob& J, int xt, char* smc, uint32_t smb)
{
    const int tid  = threadIdx.x;
    const int wid  = tid >> 5;
    const int lane = tid & 31;

    const int row0   = blockIdx.y * 128;
    const int n0     = xt * 64;
    const int kslice = n0 >> 8;
    const int wc0    = n0 & 255;

    const __half* wB1 = J.W1 + kslice * 65536;
    const __half* wB2 = J.W2 ? J.W2 + kslice * 65536 : (const __half*)0;

    const int NCH = J.nPair * 8;

    const int lrowA = tid >> 1;
    const int lkofA = (tid & 1) * 16;
    const int lrowB = tid >> 2;
    const int lkofB = (tid & 3) * 8;

    float acc[32];
#pragma unroll
    for (int i = 0; i < 32; i++) acc[i] = 0.f;

    const int wm = (wid >> 1) * 32;
    const int wn = (wid & 1) * 32;

    auto load_chunk = [&](int c, int buf) {
        const __half *pA, *pW;
        int lda;
        if (c < 8) { pA = J.A1; lda = J.lda1; pW = wB1; }
        else       { pA = J.A2; lda = J.lda2; pW = wB2; }
        const int k0 = (c & 7) * 32;
        const uint32_t sb = smb + buf * STAGE_B;
        const uint32_t soA = (lrowA * LDSE + lkofA) * 2;
        const __half* gA = pA + (size_t)(row0 + lrowA) * lda + k0 + lkofA;
        CP16(sb + soA,      gA);
        CP16(sb + soA + 16, gA + 8);
        const uint32_t soB = (lrowB * LDSE + lkofB) * 2;
        CP16(sb + A_T + soB, pW + (size_t)(wc0 + lrowB) * 256 + k0 + lkofB);
        CP_COMMIT();
    };

    load_chunk(0, 0);
    load_chunk(1, 1);

    const uint32_t aRow  = (uint32_t)(wm + (lane & 15));
    const uint32_t aKh   = (uint32_t)((lane >> 4) * 8);
    const uint32_t bRow2 = (uint32_t)(wn + (lane & 7) + ((lane >> 4) * 8));
    const uint32_t bKc   = (uint32_t)(((lane >> 3) & 1) * 8);

    for (int c = 0; c < NCH; c++) {
        if (c + 2 < NCH)      { load_chunk(c + 2, (c + 2) % 3); CP_WAIT2(); }
        else if (c + 1 < NCH) { CP_WAIT1(); }
        else                  { CP_WAIT0(); }
        __syncthreads();

        const uint32_t sb = smb + (c % 3) * STAGE_B;
#pragma unroll
        for (int ks = 0; ks < 2; ks++) {
            uint32_t a[2][4];
#pragma unroll
            for (int i = 0; i < 2; i++)
                ldm_x4(a[i], sb + ((aRow + i * 16) * LDSE + ks * 16 + aKh) * 2);
#pragma unroll
            for (int jp = 0; jp < 2; jp++) {
                uint32_t b4[4];
                const uint32_t boff = ((bRow2 + jp * 16) * LDSE + ks * 16 + bKc) * 2;
                ldm_x4(b4, sb + A_T + boff);
#pragma unroll
                for (int i = 0; i < 2; i++) {
                    mma_f16(&acc[(i * 4 + jp * 2) * 4],     a[i], b4);
                    mma_f16(&acc[(i * 4 + jp * 2 + 1) * 4], a[i], b4 + 2);
                }
            }
        }
        __syncthreads();
    }

    // epilogue: regs -> smem (128 x 68 f32) -> gmem
    float* smf = (float*)smc;
    {
        const int r0 = lane >> 2;
        const int cc = (lane & 3) * 2;
#pragma unroll
        for (int i = 0; i < 2; i++)
#pragma unroll
            for (int j = 0; j < 4; j++) {
                const float* d = &acc[(i * 4 + j) * 4];
                const int rr = wm + i * 16 + r0;
                const int col = wn + j * 8 + cc;
                smf[rr * 68 + col]           = d[0];
                smf[rr * 68 + col + 1]       = d[1];
                smf[(rr + 8) * 68 + col]     = d[2];
                smf[(rr + 8) * 68 + col + 1] = d[3];
            }
    }
    __syncthreads();

    const bool c_vec = J.C && ((((uintptr_t)J.C) & 15) == 0) && ((J.ldc & 3) == 0);

#pragma unroll
    for (int it = 0; it < 8; it++) {
        const int f4 = it * 256 + tid;
        const int rr = f4 >> 4;
        const int c4 = (f4 & 15) * 4;
        float4 v = *(float4*)&smf[rr * 68 + c4];
        const int row = row0 + rr;
        const int gn  = n0 + c4;
        float o[4];
        float dv[4] = {0.f, 0.f, 0.f, 0.f};
        if (J.mode == EPI_ADD || J.mode == EPI_MUL) {
            const __half2* dp = (const __half2*)(J.Dh + (size_t)row * J.ldd + gn);
            float2 a0 = __half22float2(dp[0]);
            float2 a1 = __half22float2(dp[1]);
            dv[0] = a0.x; dv[1] = a0.y; dv[2] = a1.x; dv[3] = a1.y;
        }
#pragma unroll
        for (int q = 0; q < 4; q++) {
            const float val = (&v.x)[q];
            const float bv = J.bias ? J.bias[gn + q] : 0.f;
            float res;
            if (J.mode == EPI_SIG)      res = 1.f / (1.f + expf(-(val + bv)));
            else if (J.mode == EPI_ADD) res = val + dv[q] + bv;
            else if (J.mode == EPI_MUL) res = val * dv[q] + bv;
            else if (J.mode == EPI_OMZ) res = 1.f - (val + bv);
            else                        res = val + bv;
            o[q] = res;
        }
        if (J.Ch) {
            __half2* cp = (__half2*)(J.Ch + (size_t)row * J.ldc + gn);
            cp[0] = __floats2half2_rn(o[0], o[1]);
            cp[1] = __floats2half2_rn(o[2], o[3]);
        } else if (J.C) {
            float* cp = J.C + (size_t)row * J.ldc + gn;
            if (c_vec) *(float4*)cp = make_float4(o[0], o[1], o[2], o[3]);
            else { cp[0] = o[0]; cp[1] = o[1]; cp[2] = o[2]; cp[3] = o[3]; }
            if (J.dupz2 && gn < 256) {
                float* zp = J.C + (size_t)row * J.ldc + 512 + gn;
                zp[0] = o[0]; zp[1] = o[1]; zp[2] = o[2]; zp[3] = o[3];
            }
        }

        if (J.C2h) {
            float o2[4];
            float dv2[4] = {0.f, 0.f, 0.f, 0.f};
            if (J.mode2 == EPI_ADD || J.mode2 == EPI_MUL) {
                const __half2* dp = (const __half2*)(J.D2h + (size_t)row * J.ldd2 + gn);
                float2 a0 = __half22float2(dp[0]);
                float2 a1 = __half22float2(dp[1]);
                dv2[0] = a0.x; dv2[1] = a0.y; dv2[2] = a1.x; dv2[3] = a1.y;
            }
#pragma unroll
            for (int q = 0; q < 4; q++) {
                const float val = (&v.x)[q];
                const float bv = J.bias ? J.bias[gn + q] : 0.f;
                float res;
                if (J.mode2 == EPI_SIG)      res = 1.f / (1.f + expf(-(val + bv)));
                else if (J.mode2 == EPI_ADD) res = val + dv2[q] + bv;
                else if (J.mode2 == EPI_MUL) res = val * dv2[q] + bv;
                else if (J.mode2 == EPI_OMZ) res = 1.f - (val + bv);
                else                         res = val + bv;
                o2[q] = res;
            }
            __half2* cp2 = (__half2*)(J.C2h + (size_t)row * J.ldc2 + gn);
            cp2[0] = __floats2half2_rn(o2[0], o2[1]);
            cp2[1] = __floats2half2_rn(o2[2], o2[3]);
        }

        if (J.Ob) {
            __half2* ph = (__half2*)(J.Ob + (size_t)row * J.ldob + gn);
            ph[0] = __floats2half2_rn(o[0], o[1]);
            ph[1] = __floats2half2_rn(o[2], o[3]);
        }
    }
}

__global__ __launch_bounds__(256, 3)
void tc_gemm2(GJob j0, GJob j1, int nx0)
{
    extern __shared__ char smc[];
    const uint32_t smb = smem_u32(smc);
    if ((int)blockIdx.x < nx0) gemm_body(j0, blockIdx.x, smc, smb);
    else                       gemm_body(j1, blockIdx.x - nx0, smc, smb);
}

// ---------------- prep: weights transpose + input convert ----------------
__global__ __launch_bounds__(256)
void prep_all(const float* __restrict__ L, const float* __restrict__ R,
              const float* __restrict__ x, const float* __restrict__ h,
              __half* __restrict__ Lh, __half* __restrict__ Rh,
              __half* __restrict__ xf, __half* __restrict__ hf)
{
    __shared__ float t[32][33];
    const int bid = blockIdx.x;
    if (bid < 512) {
        const int mz = bid >> 6;
        const int rem = bid & 63;
        const int h0 = (rem >> 3) * 32, d0 = (rem & 7) * 32;
        const float* src = (mz < 4) ? L : R;
        __half* dh = (mz < 4) ? Lh : Rh;
        const int k = mz & 3;
        const int tx = threadIdx.x & 31, ty = threadIdx.x >> 5;
        for (int i = 0; i < 32; i += 8)
            t[ty + i][tx] = src[k * 65536 + (h0 + ty + i) * 256 + d0 + tx];
        __syncthreads();
        for (int i = 0; i < 32; i += 8)
            dh[k * 65536 + (d0 + ty + i) * 256 + h0 + tx] = __float2half_rn(t[tx][ty + i]);
    } else {
        const int i = (bid - 512) * 256 + threadIdx.x;
        const int n = BATCH * HID;
        if (i < n) xf[i] = __float2half_rn(x[i]);
        else       hf[i - n] = __float2half_rn(h[i - n]);
    }
}

// ---------------- mixture (multi-job), fp16 candidates, R10 pattern ------
struct MJob {
    const __half *cand;
    const float *P, *Q;
    float *out1, *out2;
    __half *ob;
    float *rows;
    int ldcand, ldp, ldq, c3mode, ldo1;
};

__device__ __forceinline__ void mix_body(const MJob& M, int local,
                                         const float* __restrict__ b3,
                                         const float* __restrict__ Ws)
{
    const int warp = threadIdx.x >> 5;
    const int lane = threadIdx.x & 31;
    const int b = local * 8 + warp;

    const __half* cr = M.cand + (size_t)b * M.ldcand;
    const float* pr = M.P + (size_t)b * M.ldp;
    const float* qr = M.Q ? M.Q + (size_t)b * M.ldq : (const float*)0;

    float c[2][4][4];
    float s0 = 0.f, s1 = 0.f, s2 = 0.f, s3 = 0.f;

#pragma unroll
    for (int g = 0; g < 2; g++) {
        const int j = g * 128 + lane * 4;
        uint2 u0 = *(const uint2*)(cr + j);
        uint2 u1 = *(const uint2*)(cr + 256 + j);
        uint2 u2 = *(const uint2*)(cr + 512 + j);
        float2 f0a = __half22float2(*(const __half2*)&u0.x);
        float2 f0b = __half22float2(*(const __half2*)&u0.y);
        float2 f1a = __half22float2(*(const __half2*)&u1.x);
        float2 f1b = __half22float2(*(const __half2*)&u1.y);
        float2 f2a = __half22float2(*(const __half2*)&u2.x);
        float2 f2b = __half22float2(*(const __half2*)&u2.y);
        float4 bw = *(const float4*)(b3 + j);
        float4 wv = *(const float4*)(Ws + j);
        float p0 = pr[j], p1 = pr[j + 1], p2 = pr[j + 2], p3 = pr[j + 3];
        float c3v[4];
        if (M.c3mode == C3_ADD) {
            c3v[0] = p0 + qr[j]     + bw.x;
            c3v[1] = p1 + qr[j + 1] + bw.y;
            c3v[2] = p2 + qr[j + 2] + bw.z;
            c3v[3] = p3 + qr[j + 3] + bw.w;
        } else if (M.c3mode == C3_OMZ) {
            c3v[0] = 1.f - (p0 + bw.x);
            c3v[1] = 1.f - (p1 + bw.y);
            c3v[2] = 1.f - (p2 + bw.z);
            c3v[3] = 1.f - (p3 + bw.w);
        } else {
            c3v[0] = p0 * qr[j]     + bw.x;
            c3v[1] = p1 * qr[j + 1] + bw.y;
            c3v[2] = p2 * qr[j + 2] + bw.z;
            c3v[3] = p3 * qr[j + 3] + bw.w;
        }
        c[g][0][0] = f0a.x; c[g][0][1] = f0a.y; c[g][0][2] = f0b.x; c[g][0][3] = f0b.y;
        c[g][1][0] = f1a.x; c[g][1][1] = f1a.y; c[g][1][2] = f1b.x; c[g][1][3] = f1b.y;
        c[g][2][0] = f2a.x; c[g][2][1] = f2a.y; c[g][2][2] = f2b.x; c[g][2][3] = f2b.y;
        c[g][3][0] = c3v[0]; c[g][3][1] = c3v[1]; c[g][3][2] = c3v[2]; c[g][3][3] = c3v[3];
        const float w0 = wv.x, w1 = wv.y, w2 = wv.z, w3 = wv.w;
        s0 += c[g][0][0] * w0 + c[g][0][1] * w1 + c[g][0][2] * w2 + c[g][0][3] * w3;
        s1 += c[g][1][0] * w0 + c[g][1][1] * w1 + c[g][1][2] * w2 + c[g][1][3] * w3;
        s2 += c[g][2][0] * w0 + c[g][2][1] * w1 + c[g][2][2] * w2 + c[g][2][3] * w3;
        s3 += c3v[0] * w0 + c3v[1] * w1 + c3v[2] * w2 + c3v[3] * w3;
    }

#pragma unroll
    for (int o = 16; o > 0; o >>= 1) {
        s0 += __shfl_xor_sync(0xffffffffu, s0, o);
        s1 += __shfl_xor_sync(0xffffffffu, s1, o);
        s2 += __shfl_xor_sync(0xffffffffu, s2, o);
        s3 += __shfl_xor_sync(0xffffffffu, s3, o);
    }

    if (lane < 4) {
        const float sv = (lane == 0) ? s0 : (lane == 1) ? s1 : (lane == 2) ? s2 : s3;
        M.rows[lane * BATCH + b] = sv;
    }

    const float mx = fmaxf(fmaxf(s0, s1), fmaxf(s2, s3));
    const float e0 = expf(s0 - mx), e1 = expf(s1 - mx);
    const float e2 = expf(s2 - mx), e3 = expf(s3 - mx);
    const float inv = 1.f / (e0 + e1 + e2 + e3);
    const float w0 = e0 * inv, w1 = e1 * inv, w2 = e2 * inv, w3 = e3 * inv;

#pragma unroll
    for (int g = 0; g < 2; g++) {
        const int j = g * 128 + lane * 4;
        float o[4];
#pragma unroll
        for (int q = 0; q < 4; q++)
            o[q] = w0 * c[g][0][q] + w1 * c[g][1][q] + w2 * c[g][2][q] + w3 * c[g][3][q];

        float* op = M.out1 + (size_t)b * M.ldo1 + j;
        op[0] = o[0]; op[1] = o[1]; op[2] = o[2]; op[3] = o[3];
        if (M.out2)
            *(float4*)(M.out2 + (size_t)b * HID + j) = make_float4(o[0], o[1], o[2], o[3]);
        if (M.ob) {
            uint2 u;
            *(__half2*)&u.x = __floats2half2_rn(o[0], o[1]);
            *(__half2*)&u.y = __floats2half2_rn(o[2], o[3]);
            *(uint2*)(M.ob + (size_t)b * HID + j) = u;
        }
    }
}

__global__ __launch_bounds__(256)
void mix3(MJob m0, MJob m1, MJob m2, const float* b3, const float* Ws)
{
    const int jid = blockIdx.x >> 11;
    const int local = blockIdx.x & 2047;
    if (jid == 0)      mix_body(m0, local, b3, Ws);
    else if (jid == 1) mix_body(m1, local, b3, Ws);
    else               mix_body(m2, local, b3, Ws);
}

// ---------------- finalize ----------------
__global__ __launch_bounds__(256)
void fin_sum(const float* __restrict__ rs)
{
    __shared__ double tmp[256];
    const int idx = blockIdx.x;
    const int tid = threadIdx.x;
    double p = 0.0;
    for (int i = tid; i < BATCH; i += 256) p += (double)rs[idx * BATCH + i];
    tmp[tid] = p;
    __syncthreads();
    for (int o = 128; o > 0; o >>= 1) {
        if (tid < o) tmp[tid] += tmp[tid + o];
        __syncthreads();
    }
    if (tid == 0) g_ssum[idx] = tmp[0];
}

__global__ void fin_out(float* __restrict__ out)
{
    if (threadIdx.x == 0) {
        out[OFF_GS + 0] = 0.f;
        out[OFF_GS + 1] = 1.f;
        out[OFF_GS + 2] = 0.f;
        for (int s = 0; s < 6; s++) {
            double best = g_ssum[s * 4]; int bi = 0;
            for (int k = 1; k < 4; k++)
                if (g_ssum[s * 4 + k] > best) { best = g_ssum[s * 4 + k]; bi = k; }
            double second = -1e300;
            for (int k = 0; k < 4; k++)
                if (k != bi && g_ssum[s * 4 + k] > second) second = g_ssum[s * 4 + k];
            out[OFF_GS + 3 + s] = (float)bi;
            out[OFF_MARG + s]   = (float)(best - second);
        }
    }
}

// ---------------- launcher ----------------
extern "C" void kernel_launch(void* const* d_in, const int* in_sizes, int n_in,
                              void* d_out, int out_size)
{
    const float* x  = (const float*)d_in[0];
    const float* h  = (const float*)d_in[1];
    const float* L  = (const float*)d_in[2];
    const float* R  = (const float*)d_in[3];
    const float* bb = (const float*)d_in[4];
    const float* Ws = (const float*)d_in[5];
    float* out = (float*)d_out;

    static bool attr_done = false;
    if (!attr_done) {
        cudaFuncSetAttribute(tc_gemm2, cudaFuncAttributeMaxDynamicSharedMemorySize, DYN_SMEM);
        attr_done = true;
    }

    __half *p_hL, *p_tmp, *p_cand, *p_cand2, *p_hf, *p_w;
    float *p_rows;
    cudaGetSymbolAddress((void**)&p_hL,    g_hL);
    cudaGetSymbolAddress((void**)&p_tmp,   g_tmp);
    cudaGetSymbolAddress((void**)&p_cand,  g_cand);
    cudaGetSymbolAddress((void**)&p_cand2, g_cand2);
    cudaGetSymbolAddress((void**)&p_rows,  g_rows);
    cudaGetSymbolAddress((void**)&p_hf,    g_hf);
    cudaGetSymbolAddress((void**)&p_w,     g_wh);

    __half* xf   = p_hf + 0ull * UNIT;
    __half* hf   = p_hf + 1ull * UNIT;
    __half* z1r  = p_hf + 2ull * UNIT;   // 2 units, ld 512
    __half* rh   = p_hf + 4ull * UNIT;
    __half* ht   = p_hf + 5ull * UNIT;
    __half* om   = p_hf + 6ull * UNIT;
    __half* zt   = p_hf + 7ull * UNIT;
    __half* z2h  = p_hf + 8ull * UNIT;

    __half* Lh = p_w + 0ull * WUNIT;
    __half* Rh = p_w + 1ull * WUNIT;

    float* gnode = out + OFF_GNODE;
    const float* b3 = bb + 768;
    const dim3 blk(256);

    prep_all<<<512 + 2 * UNIT / 256, blk>>>(L, R, x, h, Lh, Rh, xf, hf);

    // ---- GEMM jobs
    GJob jS0{}; // [z1|r] = sig(x@L + h@R + b), N=512, fp32 -> gnode (+dup z2)
    jS0.A1 = xf; jS0.lda1 = 256; jS0.W1 = Lh;
    jS0.A2 = hf; jS0.lda2 = 256; jS0.W2 = Rh;
    jS0.nPair = 2; jS0.bias = bb;
    jS0.C = gnode; jS0.ldc = GROW; jS0.mode = EPI_SIG;
    jS0.Ob = z1r; jS0.ldob = 512; jS0.dupz2 = 1;

    GJob jHL{}; // hL = h @ L[0..2]  (fp16 scratch)
    jHL.A1 = hf; jHL.lda1 = 256; jHL.W1 = Lh;
    jHL.nPair = 1;
    jHL.Ch = p_hL; jHL.ldc = 768; jHL.mode = EPI_NONE;

    GJob jCE{}; // v = z1@R; cand_C = 1-(v+b) -> cand ; cand_E = v*hL + b -> tmp
    jCE.A1 = z1r; jCE.lda1 = 512; jCE.W1 = Rh;
    jCE.nPair = 1; jCE.bias = bb;
    jCE.Ch = p_cand; jCE.ldc = 768; jCE.mode = EPI_OMZ;
    jCE.D2h = p_hL; jCE.ldd2 = 768; jCE.C2h = p_tmp; jCE.ldc2 = 768; jCE.mode2 = EPI_MUL;

    GJob jA{};  // cand_A = r@R + hL + b -> cand2
    jA.A1 = z1r + 256; jA.lda1 = 512; jA.W1 = Rh;
    jA.nPair = 1; jA.bias = bb;
    jA.Dh = p_hL; jA.ldd = 768;
    jA.Ch = p_cand2; jA.ldc = 768; jA.mode = EPI_ADD;

    GJob jB{};  // cand_B = x@L + rh@R + b -> cand
    jB.A1 = xf; jB.lda1 = 256; jB.W1 = Lh;
    jB.A2 = rh; jB.lda2 = 256; jB.W2 = Rh;
    jB.nPair = 2; jB.bias = bb;
    jB.Ch = p_cand; jB.ldc = 768; jB.mode = EPI_NONE;

    GJob jOR{}; // omzR = omz@R -> tmp (no bias)
    jOR.A1 = om; jOR.lda1 = 256; jOR.W1 = Rh;
    jOR.nPair = 1;
    jOR.Ch = p_tmp; jOR.ldc = 768; jOR.mode = EPI_NONE;

    GJob jD{};  // cand_D = (ht@L) * omzR + b -> cand2
    jD.A1 = ht; jD.lda1 = 256; jD.W1 = Lh;
    jD.nPair = 1; jD.bias = bb;
    jD.Dh = p_tmp; jD.ldd = 768;
    jD.Ch = p_cand2; jD.ldc = 768; jD.mode = EPI_MUL;

    GJob jF{};  // cand_F = zt@L + z2h@R + b -> cand
    jF.A1 = zt; jF.lda1 = 256; jF.W1 = Lh;
    jF.A2 = z2h; jF.lda2 = 256; jF.W2 = Rh;
    jF.nPair = 2; jF.bias = bb;
    jF.Ch = p_cand; jF.ldc = 768; jF.mode = EPI_NONE;

    // ---- mix jobs
    MJob mC{}; mC.cand = p_cand; mC.ldcand = 768; mC.P = gnode; mC.ldp = GROW;
    mC.c3mode = C3_OMZ; mC.out1 = gnode + 5 * HID; mC.ldo1 = GROW;
    mC.ob = om; mC.rows = p_rows + 2 * 4 * BATCH;

    MJob mE{}; mE.cand = p_tmp; mE.ldcand = 768; mE.P = h; mE.ldp = HID;
    mE.Q = gnode; mE.ldq = GROW; mE.c3mode = C3_MUL;
    mE.out1 = gnode + 7 * HID; mE.ldo1 = GROW;
    mE.ob = z2h; mE.rows = p_rows + 4 * 4 * BATCH;

    MJob mA{}; mA.cand = p_cand2; mA.ldcand = 768; mA.P = h; mA.ldp = HID;
    mA.Q = gnode + 1 * HID; mA.ldq = GROW; mA.c3mode = C3_ADD;
    mA.out1 = gnode + 3 * HID; mA.ldo1 = GROW;
    mA.ob = rh; mA.rows = p_rows + 0 * 4 * BATCH;

    MJob mB{}; mB.cand = p_cand; mB.ldcand = 768; mB.P = x; mB.ldp = HID;
    mB.Q = gnode + 3 * HID; mB.ldq = GROW; mB.c3mode = C3_ADD;
    mB.out1 = gnode + 4 * HID; mB.ldo1 = GROW;
    mB.ob = ht; mB.rows = p_rows + 1 * 4 * BATCH;

    MJob mD{}; mD.cand = p_cand2; mD.ldcand = 768; mD.P = gnode + 4 * HID; mD.ldp = GROW;
    mD.Q = gnode + 5 * HID; mD.ldq = GROW; mD.c3mode = C3_MUL;
    mD.out1 = gnode + 6 * HID; mD.ldo1 = GROW;
    mD.ob = zt; mD.rows = p_rows + 3 * 4 * BATCH;

    MJob mF{}; mF.cand = p_cand; mF.ldcand = 768; mF.P = gnode + 6 * HID; mF.ldp = GROW;
    mF.Q = gnode + 7 * HID; mF.ldq = GROW; mF.c3mode = C3_ADD;
    mF.out1 = gnode + 8 * HID; mF.ldo1 = GROW; mF.out2 = out + OFF_HNEXT;
    mF.rows = p_rows + 5 * 4 * BATCH;

    // wave 1: stage0 (8 tiles) + hL (12 tiles)
    tc_gemm2<<<dim3(20, BATCH / 128), blk, DYN_SMEM>>>(jS0, jHL, 8);
    // wave 2: CE (12) + A (12)
    tc_gemm2<<<dim3(24, BATCH / 128), blk, DYN_SMEM>>>(jCE, jA, 12);
    // wave 3: mix C, E, A
    mix3<<<3 * 2048, blk>>>(mC, mE, mA, b3, Ws);
    // wave 4: B (12) + omzR (12)
    tc_gemm2<<<dim3(24, BATCH / 128), blk, DYN_SMEM>>>(jB, jOR, 12);
    // wave 5: mix B
    mix3<<<2048, blk>>>(mB, mB, mB, b3, Ws);
    // wave 6: D
    tc_gemm2<<<dim3(12, BATCH / 128), blk, DYN_SMEM>>>(jD, jD, 12);
    // wave 7: mix D
    mix3<<<2048, blk>>>(mD, mD, mD, b3, Ws);
    // wave 8: F
    tc_gemm2<<<dim3(12, BATCH / 128), blk, DYN_SMEM>>>(jF, jF, 12);
    // wave 9: mix F
    mix3<<<2048, blk>>>(mF, mF, mF, b3, Ws);

    fin_sum<<<24, blk>>>(p_rows);
    fin_out<<<1, 32>>>(out);
}